// round 11
// baseline (speedup 1.0000x reference)
#include <cuda_runtime.h>
#include <cuda_fp16.h>
#include <cstdint>

// Problem dims (fixed per reference setup_inputs)
#define BB 8
#define SS 2048
#define DD 512
#define II 2048
#define MM (BB*SS)   // 16384 rows (b*S+s)
#define NN (2*II)    // 4096 interleaved output cols (even=pa, odd=pi)

#define LN3 1.0986122886681098f

// GEMM tiling
#define CTA_M 128
#define CTA_N 128          // = 64 channels
#define TK 64              // K halves per chunk (128B rows)
#define NCHUNK (DD/TK)     // 8
#define STAGES 3
#define STAGE_BYTES 32768  // x 16K + Wcat 16K
#define W_OFF 16384

// Scratch
__device__ __half  g_xh[(size_t)MM * DD];    // [m, k]
__device__ __half  g_wc[(size_t)NN * DD];    // interleaved [2i+p, k]
__device__ __half2 g_ac[(size_t)MM * II];    // TRANSPOSED [i, m], packed (alpha, drive)

__device__ __forceinline__ uint32_t s2u(const void* p) {
    uint32_t a;
    asm("{ .reg .u64 t; cvta.to.shared.u64 t, %1; cvt.u32.u64 %0, t; }" : "=r"(a) : "l"(p));
    return a;
}

__device__ __forceinline__ uint32_t h2u(__half2 h) {
    uint32_t u;
    memcpy(&u, &h, 4);
    return u;
}

// SW128-style swizzle for 128-byte rows (64 halves)
__device__ __forceinline__ uint32_t swz(uint32_t o) { return o ^ ((o >> 3) & 0x70); }

__device__ __forceinline__ void cpa16(uint32_t dst, const void* src) {
    asm volatile("cp.async.cg.shared.global [%0], [%1], 16;" :: "r"(dst), "l"(src) : "memory");
}
__device__ __forceinline__ void cpa_commit() {
    asm volatile("cp.async.commit_group;" ::: "memory");
}
__device__ __forceinline__ void cpa_wait1() {
    asm volatile("cp.async.wait_group 1;" ::: "memory");
}

__device__ __forceinline__ void ldm_x4(uint32_t* r, uint32_t addr) {
    asm volatile("ldmatrix.sync.aligned.m8n8.x4.shared.b16 {%0,%1,%2,%3}, [%4];"
                 : "=r"(r[0]), "=r"(r[1]), "=r"(r[2]), "=r"(r[3]) : "r"(addr));
}

__device__ __forceinline__ void mma_f16(float* d, const uint32_t* a, uint32_t b0, uint32_t b1) {
    asm volatile(
        "mma.sync.aligned.m16n8k16.row.col.f32.f16.f16.f32 "
        "{%0,%1,%2,%3}, {%4,%5,%6,%7}, {%8,%9}, {%0,%1,%2,%3};\n"
        : "+f"(d[0]), "+f"(d[1]), "+f"(d[2]), "+f"(d[3])
        : "r"(a[0]), "r"(a[1]), "r"(a[2]), "r"(a[3]), "r"(b0), "r"(b1));
}

__device__ __forceinline__ float sigmoidf_(float v) {
    return 1.0f / (1.0f + __expf(-v));
}

// ---- fp32 -> fp16 convert (x), streaming stores ----
__global__ void cvt_kernel(const float4* __restrict__ src, __half2* __restrict__ dst, int n4)
{
    int i = blockIdx.x * blockDim.x + threadIdx.x;
    if (i < n4) {
        float4 v = __ldcs(&src[i]);
        uint2 pk = make_uint2(h2u(__floats2half2_rn(v.x, v.y)),
                              h2u(__floats2half2_rn(v.z, v.w)));
        __stcs(reinterpret_cast<uint2*>(dst) + i, pk);
    }
}

// ---- fp32 -> fp16, interleaving W rows: dst row = 2*srcrow + parity ----
__global__ void cvt_w_kernel(const float4* __restrict__ src, int parity, int n4)
{
    int i = blockIdx.x * blockDim.x + threadIdx.x;
    if (i < n4) {
        float4 v = __ldcs(&src[i]);
        int row = i >> 7;              // DD/4 = 128 float4 per row
        int c4  = i & 127;
        uint2 pk = make_uint2(h2u(__floats2half2_rn(v.x, v.y)),
                              h2u(__floats2half2_rn(v.z, v.w)));
        uint2* dst = reinterpret_cast<uint2*>(g_wc) +
                     ((size_t)(2 * row + parity) * (DD / 4) + c4);
        __stcs(dst, pk);
    }
}

// ---- GEMM: P = x @ Wcat^T (N=4096, interleaved), fused gate epilogue ----
// grid (MM/CTA_M, NN/CTA_N) = (128, 32), 256 threads (8 warps, 2x4), 2 CTAs/SM.
__global__ void __launch_bounds__(256, 2) gemm_fused_kernel(
    const float* __restrict__ ba, const float* __restrict__ bi,
    const float* __restrict__ gate)
{
    extern __shared__ char smem[];
    const uint32_t sbase = s2u(smem);

    const int tid  = threadIdx.x;
    const int wid  = tid >> 5;
    const int lane = tid & 31;
    const int wm   = wid >> 2;          // 0..1 -> 64-row slice
    const int wn   = wid & 3;           // 0..3 -> 32-col slice
    const int g    = lane >> 2;         // 0..7
    const int tg   = lane & 3;          // 0..3
    const int m_blk = blockIdx.x * CTA_M;
    const int n_blk = blockIdx.y * CTA_N;

    float acc[4][4][4];                 // [mt][nt][frag]
    #pragma unroll
    for (int mt = 0; mt < 4; mt++)
        #pragma unroll
        for (int nt = 0; nt < 4; nt++)
            #pragma unroll
            for (int r = 0; r < 4; r++) acc[mt][nt][r] = 0.f;

    // ---- base-register + immediate cp.async addressing ----
    const int r0 = tid >> 3, c0 = tid & 7;
    const uint32_t xs0 = sbase + swz(r0 * 128 + c0 * 16);
    const uint32_t ws0 = sbase + W_OFF + swz(r0 * 128 + c0 * 16);
    const __half* xg0 = g_xh + (size_t)(m_blk + r0) * DD + c0 * 8;
    const __half* wg0 = g_wc + (size_t)(n_blk + r0) * DD + c0 * 8;

    auto issue = [&](int kc, int slot) {   // kc, slot compile-time under unroll
        #pragma unroll
        for (int t = 0; t < 4; t++)
            cpa16(xs0 + slot * STAGE_BYTES + t * 4096,
                  xg0 + kc * TK + t * 32 * DD);
        #pragma unroll
        for (int t = 0; t < 4; t++)
            cpa16(ws0 + slot * STAGE_BYTES + t * 4096,
                  wg0 + kc * TK + t * 32 * DD);
        cpa_commit();
    };

    issue(0, 0); issue(1, 1);

    // Rotating current-stage absolute ldsm addresses (6 live registers).
    // swz(row*128 + kk*32 + acol) = row*128 + ((acol ^ ((row&7)<<4)) ^ kk*32)
    const int arow = lane & 15;
    const uint32_t acol = (lane >> 4) << 4;   // 0 or 16
    uint32_t aocur[4], bocur[2];
    #pragma unroll
    for (int mt = 0; mt < 4; mt++) {
        int row = wm * 64 + mt * 16 + arow;
        aocur[mt] = sbase + row * 128 + (acol ^ ((row & 7) << 4));
    }
    #pragma unroll
    for (int bt = 0; bt < 2; bt++) {
        int row = wn * 32 + bt * 16 + arow;
        bocur[bt] = sbase + W_OFF + row * 128 + (acol ^ ((row & 7) << 4));
    }

    #pragma unroll
    for (int kc = 0; kc < NCHUNK; kc++) {
        cpa_wait1();            // group kc complete
        __syncthreads();        // stage-kc visible; prior stage reads done
        if (kc + 2 < NCHUNK) issue(kc + 2, (kc + 2) % STAGES);
        else cpa_commit();      // keep group counting uniform

        // register double-buffered fragments
        uint32_t a[2][4][4], bw[2][2][4];
        #pragma unroll
        for (int mt = 0; mt < 4; mt++) ldm_x4(a[0][mt], aocur[mt]);
        #pragma unroll
        for (int bt = 0; bt < 2; bt++) ldm_x4(bw[0][bt], bocur[bt]);

        #pragma unroll
        for (int kk = 0; kk < 4; kk++) {
            const int cur = kk & 1, nxt = cur ^ 1;
            if (kk < 3) {
                const uint32_t kx = (kk + 1) * 32;     // immediate: LOP3 only
                #pragma unroll
                for (int mt = 0; mt < 4; mt++) ldm_x4(a[nxt][mt], aocur[mt] ^ kx);
                #pragma unroll
                for (int bt = 0; bt < 2; bt++) ldm_x4(bw[nxt][bt], bocur[bt] ^ kx);
            }
            #pragma unroll
            for (int mt = 0; mt < 4; mt++)
                #pragma unroll
                for (int nt = 0; nt < 4; nt++) {
                    const int bt = nt >> 1, sub = nt & 1;
                    mma_f16(acc[mt][nt], a[cur][mt], bw[cur][bt][sub], bw[cur][bt][sub + 2]);
                }
        }

        // rotate to next stage (immediates under unroll)
        const int delta = (((kc + 1) % STAGES) - (kc % STAGES)) * STAGE_BYTES;
        #pragma unroll
        for (int mt = 0; mt < 4; mt++) aocur[mt] += delta;
        #pragma unroll
        for (int bt = 0; bt < 2; bt++) bocur[bt] += delta;
    }

    // ---- fused epilogue: (c0,c1)=(pa,pi) of one channel -> half2(alpha,drive) ----
    #pragma unroll
    for (int nt = 0; nt < 4; nt++) {
        const int i = (n_blk >> 1) + wn * 16 + nt * 4 + tg;   // channel index
        const float bav = __ldg(&ba[i]);
        const float biv = __ldg(&bi[i]);
        const float alv = sigmoidf_(__ldg(&gate[i]));
        #pragma unroll
        for (int mt = 0; mt < 4; mt++) {
            const int m0 = m_blk + wm * 64 + mt * 16 + g;
            #pragma unroll
            for (int half = 0; half < 2; half++) {            // rows g, g+8
                const int m = m0 + half * 8;
                float pa = acc[mt][nt][2 * half]     + bav;
                float pi = acc[mt][nt][2 * half + 1] + biv;
                float rg = sigmoidf_(pa);
                float ig = sigmoidf_(pi);
                float aa = alv * __expf(-LN3 * rg);
                float dr = sqrtf(fmaxf(1.0f - aa * aa, 0.0f)) * (ig * pi);
                g_ac[(size_t)i * MM + m] = __floats2half2_rn(aa, dr);
            }
        }
    }
}

// ---- Sequential scan per (b,i): contiguous uint4 reads of packed (a,c) ----
// 64 s-steps per iter = 16 uint4 (256B) prefetched; streaming hints keep the
// single-use 270MB out of L2's way.
__global__ void __launch_bounds__(32) scan_kernel(float* __restrict__ out)
{
    const int idx = blockIdx.x * 32 + threadIdx.x;
    const int b = idx >> 11;
    const int i = idx & (II - 1);
    const uint4* acp = reinterpret_cast<const uint4*>(g_ac + (size_t)i * MM + b * SS);
    float* op = out + (size_t)b * SS * II + i;

    uint4 U[16], P[16];
    #pragma unroll
    for (int j = 0; j < 16; j++) U[j] = __ldcs(&acp[j]);

    float h = 0.0f;
    for (int s0 = 0; s0 < SS; s0 += 64) {
        if (s0 + 64 < SS) {
            const int q = (s0 >> 2) + 16;
            #pragma unroll
            for (int j = 0; j < 16; j++) P[j] = __ldcs(&acp[q + j]);
        }
        #pragma unroll
        for (int j = 0; j < 16; j++) {
            const uint32_t w[4] = { U[j].x, U[j].y, U[j].z, U[j].w };
            #pragma unroll
            for (int k = 0; k < 4; k++) {
                float2 p = __half22float2(*reinterpret_cast<const __half2*>(&w[k]));
                h = fmaf(p.x, h, p.y);
                __stcs(&op[(size_t)(s0 + j * 4 + k) * II], h);
            }
        }
        #pragma unroll
        for (int j = 0; j < 16; j++) U[j] = P[j];
    }
}

extern "C" void kernel_launch(void* const* d_in, const int* in_sizes, int n_in,
                              void* d_out, int out_size)
{
    const float* x    = (const float*)d_in[0];
    const float* Wa   = (const float*)d_in[1];
    const float* ba   = (const float*)d_in[2];
    const float* Wi   = (const float*)d_in[3];
    const float* bi   = (const float*)d_in[4];
    const float* gate = (const float*)d_in[5];
    float* out = (float*)d_out;

    __half* xh; cudaGetSymbolAddress((void**)&xh, g_xh);

    const int nx4 = MM * DD / 4;
    const int nw4 = II * DD / 4;
    cvt_kernel<<<(nx4 + 255) / 256, 256>>>((const float4*)x, (__half2*)xh, nx4);
    cvt_w_kernel<<<(nw4 + 255) / 256, 256>>>((const float4*)Wa, 0, nw4);
    cvt_w_kernel<<<(nw4 + 255) / 256, 256>>>((const float4*)Wi, 1, nw4);

    cudaFuncSetAttribute(gemm_fused_kernel,
                         cudaFuncAttributeMaxDynamicSharedMemorySize,
                         STAGES * STAGE_BYTES);
    dim3 grid(MM / CTA_M, NN / CTA_N);   // (128, 32)
    gemm_fused_kernel<<<grid, 256, STAGES * STAGE_BYTES>>>(ba, bi, gate);

    scan_kernel<<<(BB * II) / 32, 32>>>(out);
}

// round 13
// speedup vs baseline: 1.0353x; 1.0353x over previous
#include <cuda_runtime.h>
#include <cuda_fp16.h>
#include <cstdint>

// Problem dims (fixed per reference setup_inputs)
#define BB 8
#define SS 2048
#define DD 512
#define II 2048
#define MM (BB*SS)   // 16384 rows (b*S+s)
#define NN (2*II)    // 4096 interleaved output cols (even=pa, odd=pi)

#define LN3 1.0986122886681098f

// GEMM tiling
#define CTA_M 128
#define CTA_N 128          // = 64 channels
#define TK 64              // K halves per chunk (128B rows)
#define NCHUNK (DD/TK)     // 8
#define STAGES 3
#define STAGE_BYTES 32768  // x 16K + Wcat 16K
#define W_OFF 16384

// Scratch
__device__ __half  g_xh[(size_t)MM * DD];    // [m, k]
__device__ __half  g_wc[(size_t)NN * DD];    // interleaved [2i+p, k]
__device__ __half2 g_ac[(size_t)MM * II];    // TRANSPOSED [i, m], packed (alpha, drive)

__device__ __forceinline__ uint32_t s2u(const void* p) {
    uint32_t a;
    asm("{ .reg .u64 t; cvta.to.shared.u64 t, %1; cvt.u32.u64 %0, t; }" : "=r"(a) : "l"(p));
    return a;
}

__device__ __forceinline__ uint32_t h2u(__half2 h) {
    uint32_t u;
    memcpy(&u, &h, 4);
    return u;
}

// SW128-style swizzle for 128-byte rows (64 halves)
__device__ __forceinline__ uint32_t swz(uint32_t o) { return o ^ ((o >> 3) & 0x70); }

__device__ __forceinline__ void cpa16(uint32_t dst, const void* src) {
    asm volatile("cp.async.cg.shared.global [%0], [%1], 16;" :: "r"(dst), "l"(src) : "memory");
}
__device__ __forceinline__ void cpa_commit() {
    asm volatile("cp.async.commit_group;" ::: "memory");
}
__device__ __forceinline__ void cpa_wait1() {
    asm volatile("cp.async.wait_group 1;" ::: "memory");
}

__device__ __forceinline__ void ldm_x4(uint32_t* r, uint32_t addr) {
    asm volatile("ldmatrix.sync.aligned.m8n8.x4.shared.b16 {%0,%1,%2,%3}, [%4];"
                 : "=r"(r[0]), "=r"(r[1]), "=r"(r[2]), "=r"(r[3]) : "r"(addr));
}

__device__ __forceinline__ void mma_f16(float* d, const uint32_t* a, uint32_t b0, uint32_t b1) {
    asm volatile(
        "mma.sync.aligned.m16n8k16.row.col.f32.f16.f16.f32 "
        "{%0,%1,%2,%3}, {%4,%5,%6,%7}, {%8,%9}, {%0,%1,%2,%3};\n"
        : "+f"(d[0]), "+f"(d[1]), "+f"(d[2]), "+f"(d[3])
        : "r"(a[0]), "r"(a[1]), "r"(a[2]), "r"(a[3]), "r"(b0), "r"(b1));
}

__device__ __forceinline__ float sigmoidf_(float v) {
    return 1.0f / (1.0f + __expf(-v));
}

// ---- fp32 -> fp16 convert (x), streaming ----
__global__ void cvt_kernel(const float4* __restrict__ src, __half2* __restrict__ dst, int n4)
{
    int i = blockIdx.x * blockDim.x + threadIdx.x;
    if (i < n4) {
        float4 v = __ldcs(&src[i]);
        uint2 pk = make_uint2(h2u(__floats2half2_rn(v.x, v.y)),
                              h2u(__floats2half2_rn(v.z, v.w)));
        __stcs(reinterpret_cast<uint2*>(dst) + i, pk);
    }
}

// ---- fp32 -> fp16, interleaving W rows: dst row = 2*srcrow + parity ----
__global__ void cvt_w_kernel(const float4* __restrict__ src, int parity, int n4)
{
    int i = blockIdx.x * blockDim.x + threadIdx.x;
    if (i < n4) {
        float4 v = __ldcs(&src[i]);
        int row = i >> 7;              // DD/4 = 128 float4 per row
        int c4  = i & 127;
        uint2 pk = make_uint2(h2u(__floats2half2_rn(v.x, v.y)),
                              h2u(__floats2half2_rn(v.z, v.w)));
        uint2* dst = reinterpret_cast<uint2*>(g_wc) +
                     ((size_t)(2 * row + parity) * (DD / 4) + c4);
        __stcs(dst, pk);
    }
}

// ---- GEMM: P = x @ Wcat^T (N=4096, interleaved), fused gate epilogue ----
// grid (MM/CTA_M, NN/CTA_N) = (128, 32), 256 threads (8 warps, 2x4), 2 CTAs/SM.
__global__ void __launch_bounds__(256, 2) gemm_fused_kernel(
    const float* __restrict__ ba, const float* __restrict__ bi,
    const float* __restrict__ gate)
{
    extern __shared__ char smem[];
    const uint32_t sbase = s2u(smem);

    const int tid  = threadIdx.x;
    const int wid  = tid >> 5;
    const int lane = tid & 31;
    const int wm   = wid >> 2;          // 0..1 -> 64-row slice
    const int wn   = wid & 3;           // 0..3 -> 32-col slice
    const int g    = lane >> 2;         // 0..7
    const int tg   = lane & 3;          // 0..3
    const int m_blk = blockIdx.x * CTA_M;
    const int n_blk = blockIdx.y * CTA_N;

    float acc[4][4][4];                 // [mt][nt][frag]
    #pragma unroll
    for (int mt = 0; mt < 4; mt++)
        #pragma unroll
        for (int nt = 0; nt < 4; nt++)
            #pragma unroll
            for (int r = 0; r < 4; r++) acc[mt][nt][r] = 0.f;

    // ---- base-register + immediate cp.async addressing ----
    const int r0 = tid >> 3, c0 = tid & 7;
    const uint32_t xs0 = sbase + swz(r0 * 128 + c0 * 16);
    const uint32_t ws0 = sbase + W_OFF + swz(r0 * 128 + c0 * 16);
    const __half* xg0 = g_xh + (size_t)(m_blk + r0) * DD + c0 * 8;
    const __half* wg0 = g_wc + (size_t)(n_blk + r0) * DD + c0 * 8;

    auto issue = [&](int kc, int slot) {   // kc, slot compile-time under unroll
        #pragma unroll
        for (int t = 0; t < 4; t++)
            cpa16(xs0 + slot * STAGE_BYTES + t * 4096,
                  xg0 + kc * TK + t * 32 * DD);
        #pragma unroll
        for (int t = 0; t < 4; t++)
            cpa16(ws0 + slot * STAGE_BYTES + t * 4096,
                  wg0 + kc * TK + t * 32 * DD);
        cpa_commit();
    };

    issue(0, 0); issue(1, 1);

    // Absolute swizzled ldsm offsets. swz(row*128 + kb), kb = kk*32 + acol:
    //   = row*128 + ((acol ^ ((row&7)<<4)) ^ kk*32)   (kk bits never carry)
    const int arow = lane & 15;
    const uint32_t acol = (lane >> 4) << 4;   // 0 or 16
    uint32_t aoff[4], boff[2];
    #pragma unroll
    for (int mt = 0; mt < 4; mt++) {
        int row = wm * 64 + mt * 16 + arow;
        aoff[mt] = sbase + row * 128 + (acol ^ ((row & 7) << 4));
    }
    #pragma unroll
    for (int bt = 0; bt < 2; bt++) {
        int row = wn * 32 + bt * 16 + arow;
        boff[bt] = sbase + W_OFF + row * 128 + (acol ^ ((row & 7) << 4));
    }

    #pragma unroll
    for (int kc = 0; kc < NCHUNK; kc++) {
        cpa_wait1();            // own group kc complete (kc+1 may be in flight)
        __syncthreads();        // ALL threads' waits done -> stage-kc data visible
        if (kc + 2 < NCHUNK) issue(kc + 2, (kc + 2) % STAGES);
        else cpa_commit();      // keep group counting uniform

        const uint32_t so = (kc % STAGES) * STAGE_BYTES;   // immediate under unroll

        // register double-buffered fragments
        uint32_t a[2][4][4], bw[2][2][4];
        #pragma unroll
        for (int mt = 0; mt < 4; mt++) ldm_x4(a[0][mt], aoff[mt] + so);
        #pragma unroll
        for (int bt = 0; bt < 2; bt++) ldm_x4(bw[0][bt], boff[bt] + so);

        #pragma unroll
        for (int kk = 0; kk < 4; kk++) {
            const int cur = kk & 1, nxt = cur ^ 1;
            if (kk < 3) {
                const uint32_t kx = (kk + 1) * 32;
                #pragma unroll
                for (int mt = 0; mt < 4; mt++) ldm_x4(a[nxt][mt], (aoff[mt] + so) ^ kx);
                #pragma unroll
                for (int bt = 0; bt < 2; bt++) ldm_x4(bw[nxt][bt], (boff[bt] + so) ^ kx);
            }
            #pragma unroll
            for (int mt = 0; mt < 4; mt++)
                #pragma unroll
                for (int nt = 0; nt < 4; nt++) {
                    const int bt = nt >> 1, sub = nt & 1;
                    mma_f16(acc[mt][nt], a[cur][mt], bw[cur][bt][sub], bw[cur][bt][sub + 2]);
                }
        }
    }

    // ---- fused epilogue: (c0,c1)=(pa,pi) of one channel -> half2(alpha,drive) ----
    #pragma unroll
    for (int nt = 0; nt < 4; nt++) {
        const int i = (n_blk >> 1) + wn * 16 + nt * 4 + tg;   // channel index
        const float bav = __ldg(&ba[i]);
        const float biv = __ldg(&bi[i]);
        const float alv = sigmoidf_(__ldg(&gate[i]));
        #pragma unroll
        for (int mt = 0; mt < 4; mt++) {
            const int m0 = m_blk + wm * 64 + mt * 16 + g;
            #pragma unroll
            for (int half = 0; half < 2; half++) {            // rows g, g+8
                const int m = m0 + half * 8;
                float pa = acc[mt][nt][2 * half]     + bav;
                float pi = acc[mt][nt][2 * half + 1] + biv;
                float rg = sigmoidf_(pa);
                float ig = sigmoidf_(pi);
                float aa = alv * __expf(-LN3 * rg);
                float dr = sqrtf(fmaxf(1.0f - aa * aa, 0.0f)) * (ig * pi);
                g_ac[(size_t)i * MM + m] = __floats2half2_rn(aa, dr);
            }
        }
    }
}

// ---- Sequential scan per (b,i): contiguous uint4 reads of packed (a,c) ----
// 64 s-steps per iter = 16 uint4 (256B) prefetched; streaming hints keep the
// single-use 270MB out of L2's way.
__global__ void __launch_bounds__(32) scan_kernel(float* __restrict__ out)
{
    const int idx = blockIdx.x * 32 + threadIdx.x;
    const int b = idx >> 11;
    const int i = idx & (II - 1);
    const uint4* acp = reinterpret_cast<const uint4*>(g_ac + (size_t)i * MM + b * SS);
    float* op = out + (size_t)b * SS * II + i;

    uint4 U[16], P[16];
    #pragma unroll
    for (int j = 0; j < 16; j++) U[j] = __ldcs(&acp[j]);

    float h = 0.0f;
    for (int s0 = 0; s0 < SS; s0 += 64) {
        if (s0 + 64 < SS) {
            const int q = (s0 >> 2) + 16;
            #pragma unroll
            for (int j = 0; j < 16; j++) P[j] = __ldcs(&acp[q + j]);
        }
        #pragma unroll
        for (int j = 0; j < 16; j++) {
            const uint32_t w[4] = { U[j].x, U[j].y, U[j].z, U[j].w };
            #pragma unroll
            for (int k = 0; k < 4; k++) {
                float2 p = __half22float2(*reinterpret_cast<const __half2*>(&w[k]));
                h = fmaf(p.x, h, p.y);
                __stcs(&op[(size_t)(s0 + j * 4 + k) * II], h);
            }
        }
        #pragma unroll
        for (int j = 0; j < 16; j++) U[j] = P[j];
    }
}

extern "C" void kernel_launch(void* const* d_in, const int* in_sizes, int n_in,
                              void* d_out, int out_size)
{
    const float* x    = (const float*)d_in[0];
    const float* Wa   = (const float*)d_in[1];
    const float* ba   = (const float*)d_in[2];
    const float* Wi   = (const float*)d_in[3];
    const float* bi   = (const float*)d_in[4];
    const float* gate = (const float*)d_in[5];
    float* out = (float*)d_out;

    __half* xh; cudaGetSymbolAddress((void**)&xh, g_xh);

    const int nx4 = MM * DD / 4;
    const int nw4 = II * DD / 4;
    cvt_kernel<<<(nx4 + 255) / 256, 256>>>((const float4*)x, (__half2*)xh, nx4);
    cvt_w_kernel<<<(nw4 + 255) / 256, 256>>>((const float4*)Wa, 0, nw4);
    cvt_w_kernel<<<(nw4 + 255) / 256, 256>>>((const float4*)Wi, 1, nw4);

    cudaFuncSetAttribute(gemm_fused_kernel,
                         cudaFuncAttributeMaxDynamicSharedMemorySize,
                         STAGES * STAGE_BYTES);
    dim3 grid(MM / CTA_M, NN / CTA_N);   // (128, 32)
    gemm_fused_kernel<<<grid, 256, STAGES * STAGE_BYTES>>>(ba, bi, gate);

    scan_kernel<<<(BB * II) / 32, 32>>>(out);
}